// round 2
// baseline (speedup 1.0000x reference)
#include <cuda_runtime.h>
#include <cuda_bf16.h>

// Problem constants
#define N_    8
#define C_    256
#define H_    64
#define W_    64
#define OUTC  256
#define KK    9            // KH*KW
#define OH    64
#define OW    64
#define M_    (N_*OH*OW)   // 32768 pixels
#define RDIM  (C_*KK)      // 2304 reduction

// Precomputed bilinear params: layout [k][m] (m = n*4096 + oh*64 + ow)
__device__ float4 d_wgt[KK * M_];
__device__ int4   d_idx[KK * M_];

__global__ __launch_bounds__(256) void prep_kernel(const float* __restrict__ off) {
    int t = blockIdx.x * 256 + threadIdx.x;
    if (t >= KK * M_) return;
    int k   = t >> 15;        // t / 32768
    int m   = t & (M_/KK==0?0:32767);
    int n   = m >> 12;        // m / 4096
    int pix = m & 4095;
    int oh  = pix >> 6;
    int ow  = pix & 63;

    // offset tensor: (N, 2K, OH, OW); channel 2k = dy, 2k+1 = dx
    float offy = off[(((n * 18) + 2 * k    ) << 12) + pix];
    float offx = off[(((n * 18) + 2 * k + 1) << 12) + pix];

    float y  = (float)(k / 3 - 1 + oh) + offy;   // PAD=1, STRIDE=1
    float xq = (float)(k % 3 - 1 + ow) + offx;

    float y0f = floorf(y), x0f = floorf(xq);
    float fy = y - y0f, fx = xq - x0f;
    int y0 = (int)y0f, x0 = (int)x0f;
    int y1 = y0 + 1,   x1 = x0 + 1;

    float vy0 = (y0 >= 0 && y0 <= H_-1) ? 1.f : 0.f;
    float vy1 = (y1 >= 0 && y1 <= H_-1) ? 1.f : 0.f;
    float vx0 = (x0 >= 0 && x0 <= W_-1) ? 1.f : 0.f;
    float vx1 = (x1 >= 0 && x1 <= W_-1) ? 1.f : 0.f;

    float wy0 = 1.f - fy, wy1 = fy;
    float wx0 = 1.f - fx, wx1 = fx;

    float4 wv;
    wv.x = wy0 * wx0 * vy0 * vx0;
    wv.y = wy0 * wx1 * vy0 * vx1;
    wv.z = wy1 * wx0 * vy1 * vx0;
    wv.w = wy1 * wx1 * vy1 * vx1;

    int yc0 = min(max(y0, 0), H_-1), yc1 = min(max(y1, 0), H_-1);
    int xc0 = min(max(x0, 0), W_-1), xc1 = min(max(x1, 0), W_-1);
    int4 iv;
    iv.x = yc0 * W_ + xc0;
    iv.y = yc0 * W_ + xc1;
    iv.z = yc1 * W_ + xc0;
    iv.w = yc1 * W_ + xc1;

    d_wgt[t] = wv;
    d_idx[t] = iv;
}

// Fused implicit GEMM: D[M, OUTC] = A[M, RDIM] * W^T, A built on-the-fly by gather.
// r = c*9 + k  (matches weight [o][c][kh][kw] row-major: w[o*2304 + r])
#define BM 128
#define BN 128
#define BK 16

__global__ __launch_bounds__(256) void dgemm_kernel(
    const float* __restrict__ x,      // (N, C, H, W)
    const float* __restrict__ w,      // (OUTC, C, 3, 3) = [o][2304]
    float* __restrict__ out)          // (N, OUTC, OH, OW)
{
    __shared__ float As[BK][BM];
    __shared__ float Bs[BK][BN + 4];

    int tid = threadIdx.x;
    int m0 = blockIdx.x * BM;
    int o0 = blockIdx.y * BN;
    int tx = tid & 15;       // o micro-tile
    int ty = tid >> 4;       // m micro-tile

    float acc[8][8];
    #pragma unroll
    for (int i = 0; i < 8; i++)
        #pragma unroll
        for (int j = 0; j < 8; j++) acc[i][j] = 0.f;

    // each thread owns fixed mi for A loads
    int mi = tid & 127;
    int ri_base = tid >> 7;                 // 0 or 1
    int mA = m0 + mi;
    const float* xn = x + ((size_t)(mA >> 12) * C_) * (H_ * W_);  // n-slice of x

    for (int r0 = 0; r0 < RDIM; r0 += BK) {
        // ---- load A tile (gather): 128x16, 8 elems/thread ----
        #pragma unroll
        for (int i = 0; i < 8; i++) {
            int ri = ri_base + 2 * i;
            int r = r0 + ri;
            int c = r / 9;
            int k = r - c * 9;
            int p = (k << 15) + mA;          // k*32768 + m
            float4 wv = d_wgt[p];
            int4   iv = d_idx[p];
            const float* xp = xn + ((size_t)c << 12);
            float a = wv.x * __ldg(xp + iv.x)
                    + wv.y * __ldg(xp + iv.y)
                    + wv.z * __ldg(xp + iv.z)
                    + wv.w * __ldg(xp + iv.w);
            As[ri][mi] = a;
        }
        // ---- load B tile: 128 o x 16 r ----
        {
            int riB = tid & 15;
            int oiB = tid >> 4;
            #pragma unroll
            for (int i = 0; i < 8; i++) {
                int oi = oiB + 16 * i;
                Bs[riB][oi] = w[(size_t)(o0 + oi) * RDIM + r0 + riB];
            }
        }
        __syncthreads();

        // ---- compute ----
        #pragma unroll
        for (int ri = 0; ri < BK; ri++) {
            float4 a0 = *(const float4*)&As[ri][ty * 8];
            float4 a1 = *(const float4*)&As[ri][ty * 8 + 4];
            float4 b0 = *(const float4*)&Bs[ri][tx * 8];
            float4 b1 = *(const float4*)&Bs[ri][tx * 8 + 4];
            float a[8] = {a0.x, a0.y, a0.z, a0.w, a1.x, a1.y, a1.z, a1.w};
            float b[8] = {b0.x, b0.y, b0.z, b0.w, b1.x, b1.y, b1.z, b1.w};
            #pragma unroll
            for (int ii = 0; ii < 8; ii++)
                #pragma unroll
                for (int jj = 0; jj < 8; jj++)
                    acc[ii][jj] += a[ii] * b[jj];
        }
        __syncthreads();
    }

    // ---- epilogue: out[n][o][pix], contiguous float4 along pix ----
    int pixb = (m0 & 4095) + ty * 8;
    size_t nbase = (size_t)(m0 >> 12) * OUTC * (OH * OW);
    #pragma unroll
    for (int jj = 0; jj < 8; jj++) {
        int o = o0 + tx * 8 + jj;
        float* op = out + nbase + (size_t)o * (OH * OW) + pixb;
        float4 v0 = make_float4(acc[0][jj], acc[1][jj], acc[2][jj], acc[3][jj]);
        float4 v1 = make_float4(acc[4][jj], acc[5][jj], acc[6][jj], acc[7][jj]);
        *(float4*)op       = v0;
        *(float4*)(op + 4) = v1;
    }
}

extern "C" void kernel_launch(void* const* d_in, const int* in_sizes, int n_in,
                              void* d_out, int out_size) {
    const float* x   = (const float*)d_in[0];
    const float* off = (const float*)d_in[1];
    const float* w   = (const float*)d_in[2];
    float* out = (float*)d_out;

    prep_kernel<<<(KK * M_ + 255) / 256, 256>>>(off);

    dim3 grid(M_ / BM, OUTC / BN);
    dgemm_kernel<<<grid, 256>>>(x, w, out);
}

// round 5
// speedup vs baseline: 2.1993x; 2.1993x over previous
#include <cuda_runtime.h>
#include <cuda_bf16.h>
#include <cstdint>

// Problem constants
#define N_    8
#define C_    256
#define H_    64
#define W_    64
#define OUTC  256
#define KK    9
#define OH    64
#define OW    64
#define M_    (N_*OH*OW)   // 32768
#define RDIM  (C_*KK)      // 2304
#define BK    32
#define NITER (RDIM/BK)    // 72

// ---------------- static device scratch ----------------
__device__ float4 d_wgt[KK * M_];          // 4.7 MB
__device__ int4   d_idx[KK * M_];          // 4.7 MB
__device__ float  d_A[(size_t)M_ * RDIM];  // 302 MB  gathered im2col (tf32-rounded)
__device__ float  d_wtf[OUTC * RDIM];      // 2.3 MB  tf32-rounded weights

__device__ __forceinline__ float tf32r(float f) {
    uint32_t u;
    asm("cvt.rna.tf32.f32 %0, %1;" : "=r"(u) : "f"(f));
    return __uint_as_float(u);
}
__device__ __forceinline__ uint32_t smem_u32(const void* p) {
    uint32_t a;
    asm("{ .reg .u64 t; cvta.to.shared.u64 t, %1; cvt.u32.u64 %0, t; }" : "=r"(a) : "l"(p));
    return a;
}

// ---------------- kernel 1: bilinear params ----------------
__global__ __launch_bounds__(256) void prep_kernel(const float* __restrict__ off) {
    int t = blockIdx.x * 256 + threadIdx.x;
    if (t >= KK * M_) return;
    int k   = t >> 15;
    int m   = t & 32767;
    int n   = m >> 12;
    int pix = m & 4095;
    int oh  = pix >> 6;
    int ow  = pix & 63;

    float offy = off[(((n * 18) + 2 * k    ) << 12) + pix];
    float offx = off[(((n * 18) + 2 * k + 1) << 12) + pix];

    float y  = (float)(k / 3 - 1 + oh) + offy;
    float xq = (float)(k % 3 - 1 + ow) + offx;

    float y0f = floorf(y), x0f = floorf(xq);
    float fy = y - y0f, fx = xq - x0f;
    int y0 = (int)y0f, x0 = (int)x0f;
    int y1 = y0 + 1,   x1 = x0 + 1;

    float vy0 = (y0 >= 0 && y0 <= H_-1) ? 1.f : 0.f;
    float vy1 = (y1 >= 0 && y1 <= H_-1) ? 1.f : 0.f;
    float vx0 = (x0 >= 0 && x0 <= W_-1) ? 1.f : 0.f;
    float vx1 = (x1 >= 0 && x1 <= W_-1) ? 1.f : 0.f;

    float wy0 = 1.f - fy, wy1 = fy;
    float wx0 = 1.f - fx, wx1 = fx;

    float4 wv;
    wv.x = wy0 * wx0 * vy0 * vx0;
    wv.y = wy0 * wx1 * vy0 * vx1;
    wv.z = wy1 * wx0 * vy1 * vx0;
    wv.w = wy1 * wx1 * vy1 * vx1;

    int yc0 = min(max(y0, 0), H_-1), yc1 = min(max(y1, 0), H_-1);
    int xc0 = min(max(x0, 0), W_-1), xc1 = min(max(x1, 0), W_-1);
    int4 iv;
    iv.x = yc0 * W_ + xc0;
    iv.y = yc0 * W_ + xc1;
    iv.z = yc1 * W_ + xc0;
    iv.w = yc1 * W_ + xc1;

    d_wgt[t] = wv;
    d_idx[t] = iv;
}

// ---------------- kernel 2: round weights to tf32 ----------------
__global__ __launch_bounds__(256) void wprep_kernel(const float* __restrict__ w) {
    int i = blockIdx.x * 256 + threadIdx.x;
    if (i >= OUTC * RDIM / 4) return;
    float4 v = ((const float4*)w)[i];
    v.x = tf32r(v.x); v.y = tf32r(v.y); v.z = tf32r(v.z); v.w = tf32r(v.w);
    ((float4*)d_wtf)[i] = v;
}

// ---------------- kernel 3: gather im2col -> d_A ----------------
// block = 32 pixels x 8 r-quads, loops over 72 k-chunks
__global__ __launch_bounds__(256) void gather_kernel(const float* __restrict__ x) {
    int tid = threadIdx.x;
    int mi  = tid & 31;
    int q   = tid >> 5;          // 0..7
    int m   = (blockIdx.x << 5) + mi;
    const float* xn = x + (size_t)(m >> 12) * (C_ * 4096);
    float* arow = d_A + (size_t)m * RDIM;

    for (int rc = 0; rc < NITER; ++rc) {
        float v[4];
        #pragma unroll
        for (int e = 0; e < 4; ++e) {
            int r = rc * 32 + q * 4 + e;
            int c = r / 9;
            int k = r - c * 9;
            int p = (k << 15) + m;
            float4 wv = d_wgt[p];
            int4   iv = d_idx[p];
            const float* xp = xn + ((size_t)c << 12);
            float a = wv.x * __ldg(xp + iv.x)
                    + wv.y * __ldg(xp + iv.y)
                    + wv.z * __ldg(xp + iv.z)
                    + wv.w * __ldg(xp + iv.w);
            v[e] = tf32r(a);
        }
        *(float4*)(arow + rc * 32 + q * 4) = make_float4(v[0], v[1], v[2], v[3]);
    }
}

// ---------------- kernel 4: GEMM via mma.sync tf32 ----------------
// D[o=256][m-tile=128] = W[256][2304] * A[m][2304]^T
// 512 threads, warp tile 64o x 32m, k-chunk 32, cp.async double buffer
#define PADF 36                            // floats per smem row (bank-conflict-free, 16B aligned)
#define A_ST (256 * PADF)                  // weights stage, floats
#define B_ST (128 * PADF)                  // pixels stage, floats
#define STAGE (A_ST + B_ST)
#define SMEM_BYTES (2 * STAGE * 4)

__device__ __forceinline__ void cp16(uint32_t dst, const float* src) {
    asm volatile("cp.async.cg.shared.global [%0], [%1], 16;" :: "r"(dst), "l"(src) : "memory");
}

__global__ __launch_bounds__(512, 1) void gemm_kernel(float* __restrict__ out) {
    extern __shared__ float smem[];
    uint32_t sbase = smem_u32(smem);

    int tid  = threadIdx.x;
    int wid  = tid >> 5;
    int lane = tid & 31;
    int g    = lane >> 2;       // group id (0..7)
    int tg   = lane & 3;        // thread in group
    int wm   = wid & 3;         // o-warp   (64 o each)
    int wn   = wid >> 2;        // pix-warp (32 m each)
    int m0   = blockIdx.x << 7;

    float acc[4][4][4];
    #pragma unroll
    for (int i = 0; i < 4; i++)
        #pragma unroll
        for (int j = 0; j < 4; j++)
            #pragma unroll
            for (int e = 0; e < 4; e++) acc[i][j][e] = 0.f;

    // cp.async load of one k-chunk into stage s
    auto load_tile = [&](int rc, int s) {
        uint32_t stg = sbase + s * (STAGE * 4);
        #pragma unroll
        for (int t = 0; t < 6; ++t) {
            int i = tid + (t << 9);       // 0..3071
            if (i < 2048) {               // weights: 256 rows x 8 chunks
                int o = i >> 3, j = i & 7;
                cp16(stg + (o * PADF + j * 4) * 4,
                     d_wtf + (size_t)o * RDIM + rc * 32 + j * 4);
            } else {                      // pixels: 128 rows x 8 chunks
                int ii = i - 2048;
                int p = ii >> 3, j = ii & 7;
                cp16(stg + (A_ST + p * PADF + j * 4) * 4,
                     d_A + (size_t)(m0 + p) * RDIM + rc * 32 + j * 4);
            }
        }
    };

    load_tile(0, 0);
    asm volatile("cp.async.commit_group;" ::: "memory");

    for (int it = 0; it < NITER; ++it) {
        if (it + 1 < NITER) {
            load_tile(it + 1, (it + 1) & 1);
            asm volatile("cp.async.commit_group;" ::: "memory");
            asm volatile("cp.async.wait_group 1;" ::: "memory");
        } else {
            asm volatile("cp.async.wait_group 0;" ::: "memory");
        }
        __syncthreads();

        const float* As = smem + (it & 1) * STAGE;          // [256][PADF] weights
        const float* Bs = As + A_ST;                        // [128][PADF] pixels

        #pragma unroll
        for (int ks = 0; ks < 4; ++ks) {
            uint32_t a[4][4], b[4][2];
            int ac = ks * 8 + tg;
            #pragma unroll
            for (int mf = 0; mf < 4; ++mf) {
                const float* ap = As + (wm * 64 + mf * 16 + g) * PADF + ac;
                a[mf][0] = __float_as_uint(ap[0]);
                a[mf][1] = __float_as_uint(ap[8 * PADF]);
                a[mf][2] = __float_as_uint(ap[4]);
                a[mf][3] = __float_as_uint(ap[8 * PADF + 4]);
            }
            #pragma unroll
            for (int nf = 0; nf < 4; ++nf) {
                const float* bp = Bs + (wn * 32 + nf * 8 + g) * PADF + ac;
                b[nf][0] = __float_as_uint(bp[0]);
                b[nf][1] = __float_as_uint(bp[4]);
            }
            #pragma unroll
            for (int mf = 0; mf < 4; ++mf)
                #pragma unroll
                for (int nf = 0; nf < 4; ++nf) {
                    asm volatile(
                        "mma.sync.aligned.m16n8k8.row.col.f32.tf32.tf32.f32 "
                        "{%0,%1,%2,%3}, {%4,%5,%6,%7}, {%8,%9}, {%0,%1,%2,%3};"
                        : "+f"(acc[mf][nf][0]), "+f"(acc[mf][nf][1]),
                          "+f"(acc[mf][nf][2]), "+f"(acc[mf][nf][3])
                        : "r"(a[mf][0]), "r"(a[mf][1]), "r"(a[mf][2]), "r"(a[mf][3]),
                          "r"(b[nf][0]), "r"(b[nf][1]));
                }
        }
        __syncthreads();
    }

    // ---- epilogue: D row = o, col = pixel -> coalesced float2 stores ----
    int nimg   = m0 >> 12;
    int pixoff = m0 & 4095;
    float* ob  = out + (size_t)nimg * (OUTC * 4096) + pixoff;
    #pragma unroll
    for (int mf = 0; mf < 4; ++mf) {
        #pragma unroll
        for (int nf = 0; nf < 4; ++nf) {
            int o   = wm * 64 + mf * 16 + g;
            int col = wn * 32 + nf * 8 + 2 * tg;
            *(float2*)(ob + (size_t)o * 4096 + col) =
                make_float2(acc[mf][nf][0], acc[mf][nf][1]);
            *(float2*)(ob + (size_t)(o + 8) * 4096 + col) =
                make_float2(acc[mf][nf][2], acc[mf][nf][3]);
        }
    }
}

extern "C" void kernel_launch(void* const* d_in, const int* in_sizes, int n_in,
                              void* d_out, int out_size) {
    const float* x   = (const float*)d_in[0];
    const float* off = (const float*)d_in[1];
    const float* w   = (const float*)d_in[2];
    float* out = (float*)d_out;

    cudaFuncSetAttribute(gemm_kernel, cudaFuncAttributeMaxDynamicSharedMemorySize, SMEM_BYTES);

    prep_kernel<<<(KK * M_ + 255) / 256, 256>>>(off);
    wprep_kernel<<<(OUTC * RDIM / 4 + 255) / 256, 256>>>(w);
    gather_kernel<<<M_ / 32, 256>>>(x);
    gemm_kernel<<<M_ / 128, 512, SMEM_BYTES>>>(out);
}

// round 9
// speedup vs baseline: 2.2648x; 1.0298x over previous
#include <cuda_runtime.h>
#include <cuda_bf16.h>
#include <cstdint>

// Problem constants
#define N_    8
#define C_    256
#define H_    64
#define W_    64
#define OUTC  256
#define KK    9
#define OH    64
#define OW    64
#define M_    (N_*OH*OW)   // 32768
#define RDIM  (C_*KK)      // 2304
#define NITER (RDIM/32)    // 72

// ---------------- static device scratch ----------------
__device__ float4 d_wgt[KK * M_];          // bilinear weights  [k][m]
__device__ int4   d_idx[KK * M_];          // bilinear indices  [k][m]
__device__ float  d_wtf[OUTC * RDIM];      // tf32-rounded, k-pair-permuted weights

__device__ __forceinline__ float tf32r(float f) {
    uint32_t u;
    asm("cvt.rna.tf32.f32 %0, %1;" : "=r"(u) : "f"(f));
    return __uint_as_float(u);
}
__device__ __forceinline__ uint32_t smem_u32(const void* p) {
    uint32_t a;
    asm("{ .reg .u64 t; cvta.to.shared.u64 t, %1; cvt.u32.u64 %0, t; }" : "=r"(a) : "l"(p));
    return a;
}
__device__ __forceinline__ void cp16(uint32_t dst, const float* src) {
    asm volatile("cp.async.cg.shared.global [%0], [%1], 16;" :: "r"(dst), "l"(src) : "memory");
}

// ---------------- kernel 1: bilinear params ----------------
__global__ __launch_bounds__(256) void prep_kernel(const float* __restrict__ off) {
    int t = blockIdx.x * 256 + threadIdx.x;
    if (t >= KK * M_) return;
    int k   = t >> 15;
    int m   = t & 32767;
    int n   = m >> 12;
    int pix = m & 4095;
    int oh  = pix >> 6;
    int ow  = pix & 63;

    float offy = off[(((n * 18) + 2 * k    ) << 12) + pix];
    float offx = off[(((n * 18) + 2 * k + 1) << 12) + pix];

    float y  = (float)(k / 3 - 1 + oh) + offy;
    float xq = (float)(k % 3 - 1 + ow) + offx;

    float y0f = floorf(y), x0f = floorf(xq);
    float fy = y - y0f, fx = xq - x0f;
    int y0 = (int)y0f, x0 = (int)x0f;
    int y1 = y0 + 1,   x1 = x0 + 1;

    float vy0 = (y0 >= 0 && y0 <= H_-1) ? 1.f : 0.f;
    float vy1 = (y1 >= 0 && y1 <= H_-1) ? 1.f : 0.f;
    float vx0 = (x0 >= 0 && x0 <= W_-1) ? 1.f : 0.f;
    float vx1 = (x1 >= 0 && x1 <= W_-1) ? 1.f : 0.f;

    float wy0 = 1.f - fy, wy1 = fy;
    float wx0 = 1.f - fx, wx1 = fx;

    float4 wv;
    wv.x = wy0 * wx0 * vy0 * vx0;
    wv.y = wy0 * wx1 * vy0 * vx1;
    wv.z = wy1 * wx0 * vy1 * vx0;
    wv.w = wy1 * wx1 * vy1 * vx1;

    int yc0 = min(max(y0, 0), H_-1), yc1 = min(max(y1, 0), H_-1);
    int xc0 = min(max(x0, 0), W_-1), xc1 = min(max(x1, 0), W_-1);
    int4 iv;
    iv.x = yc0 * W_ + xc0;
    iv.y = yc0 * W_ + xc1;
    iv.z = yc1 * W_ + xc0;
    iv.w = yc1 * W_ + xc1;

    d_wgt[t] = wv;
    d_idx[t] = iv;
}

// ---------------- kernel 2: round + k-pair-permute weights ----------------
// phys col within each 8-group: pc&7 = w8; holds logical k = g8*8 + (w8>>1) + (w8&1)*4
__global__ __launch_bounds__(256) void wprep_kernel(const float* __restrict__ w) {
    int i = blockIdx.x * 256 + threadIdx.x;
    if (i >= OUTC * RDIM) return;
    int o  = i / RDIM;
    int pc = i - o * RDIM;
    int g8 = pc >> 3, w8 = pc & 7;
    int lk = g8 * 8 + (w8 >> 1) + ((w8 & 1) << 2);
    d_wtf[i] = tf32r(w[o * RDIM + lk]);
}

// ---------------- kernel 3: fused gather + GEMM (mma.sync tf32) ----------------
// CTA: o=256 (full) x m=128 pixels, k-chunk 32. 512 threads, warp tile 64o x 32m.
// smem: W0/W1 = 256x128B (weights, 2 stages), P0/P1 = 128x128B (gathered pixels)
#define SMEM_BYTES (32768*2 + 16384*2)

__global__ __launch_bounds__(512, 1) void fused_kernel(
    const float* __restrict__ x, float* __restrict__ out)
{
    extern __shared__ char smem[];
    uint32_t sb = smem_u32(smem);
    uint32_t Wb[2] = { sb, sb + 32768 };
    uint32_t Pb[2] = { sb + 65536, sb + 81920 };

    int tid  = threadIdx.x;
    int wid  = tid >> 5;
    int lane = tid & 31;
    int g    = lane >> 2;
    int tg   = lane & 3;
    int wm   = wid & 3;          // o-warp (64 each)
    int wn   = wid >> 2;         // m-warp (32 each)

    int m0   = blockIdx.x << 7;
    int mi   = tid & 127;        // gather pixel
    int rsel = tid >> 7;         // gather k-pair slot (0..3)
    int mA   = m0 + mi;
    const float* xn = x + (size_t)(mA >> 12) * (C_ * 4096);

    float acc[4][4][4];
    #pragma unroll
    for (int i = 0; i < 4; i++)
        #pragma unroll
        for (int j = 0; j < 4; j++)
            #pragma unroll
            for (int e = 0; e < 4; e++) acc[i][j][e] = 0.f;

    // -------- helper: cp.async one weight k-chunk --------
    auto cp_weights = [&](int rc, uint32_t Wt) {
        #pragma unroll
        for (int t = 0; t < 4; t++) {
            int ch  = tid + (t << 9);       // 0..2047 16B-chunks
            int o   = ch >> 3;
            int c16 = ch & 7;
            uint32_t dst = Wt + o * 128 + ((c16 ^ (o & 7)) << 4);
            cp16(dst, d_wtf + (size_t)o * RDIM + rc * 32 + c16 * 4);
        }
    };

    // -------- helper: issue gather loads for half hg (4 elems) --------
    auto gather_half = [&](int rc, int hg, float4* wq, float4* tp) {
        #pragma unroll
        for (int u = 0; u < 4; u++) {
            int gg = hg * 2 + (u >> 1);
            int e  = u & 1;
            int r  = rc * 32 + gg * 8 + rsel + e * 4;
            int c  = r / 9;
            int kk = r - c * 9;
            int p  = (kk << 15) + mA;
            wq[u] = d_wgt[p];
            int4 iv = d_idx[p];
            const float* xp = xn + ((size_t)c << 12);
            tp[u].x = __ldg(xp + iv.x);
            tp[u].y = __ldg(xp + iv.y);
            tp[u].z = __ldg(xp + iv.z);
            tp[u].w = __ldg(xp + iv.w);
        }
    };

    // -------- helper: bilinear + STS for half hg --------
    auto finish_half = [&](int hg, const float4* wq, const float4* tp, uint32_t Pt) {
        #pragma unroll
        for (int q = 0; q < 2; q++) {
            int gg = hg * 2 + q;
            float v0 = tf32r(wq[2*q].x * tp[2*q].x + wq[2*q].y * tp[2*q].y
                           + wq[2*q].z * tp[2*q].z + wq[2*q].w * tp[2*q].w);
            float v1 = tf32r(wq[2*q+1].x * tp[2*q+1].x + wq[2*q+1].y * tp[2*q+1].y
                           + wq[2*q+1].z * tp[2*q+1].z + wq[2*q+1].w * tp[2*q+1].w);
            int c16 = gg * 2 + (rsel >> 1);
            uint32_t a = Pt + mi * 128 + ((c16 ^ (mi & 7)) << 4) + ((rsel & 1) << 3);
            asm volatile("st.shared.v2.f32 [%0], {%1,%2};" :: "r"(a), "f"(v0), "f"(v1) : "memory");
        }
    };

    // -------- helper: MMAs for two k-steps --------
    auto mma_half = [&](uint32_t Wt, uint32_t Pt, int ks0) {
        #pragma unroll
        for (int ks = ks0; ks < ks0 + 2; ks++) {
            int cu = ks * 2 + (tg >> 1);
            int hb = (tg & 1) << 3;
            uint32_t a[4][4], b[4][2];
            #pragma unroll
            for (int mf = 0; mf < 4; mf++) {
                int r0 = wm * 64 + mf * 16 + g;
                int r1 = r0 + 8;
                uint32_t a0 = Wt + r0 * 128 + ((cu ^ (r0 & 7)) << 4) + hb;
                uint32_t a1 = Wt + r1 * 128 + ((cu ^ (r1 & 7)) << 4) + hb;
                asm volatile("ld.shared.v2.b32 {%0,%1}, [%2];" : "=r"(a[mf][0]), "=r"(a[mf][2]) : "r"(a0));
                asm volatile("ld.shared.v2.b32 {%0,%1}, [%2];" : "=r"(a[mf][1]), "=r"(a[mf][3]) : "r"(a1));
            }
            #pragma unroll
            for (int nf = 0; nf < 4; nf++) {
                int rr = wn * 32 + nf * 8 + g;
                uint32_t bd = Pt + rr * 128 + ((cu ^ (rr & 7)) << 4) + hb;
                asm volatile("ld.shared.v2.b32 {%0,%1}, [%2];" : "=r"(b[nf][0]), "=r"(b[nf][1]) : "r"(bd));
            }
            #pragma unroll
            for (int mf = 0; mf < 4; mf++)
                #pragma unroll
                for (int nf = 0; nf < 4; nf++) {
                    asm volatile(
                        "mma.sync.aligned.m16n8k8.row.col.f32.tf32.tf32.f32 "
                        "{%0,%1,%2,%3}, {%4,%5,%6,%7}, {%8,%9}, {%0,%1,%2,%3};"
                        : "+f"(acc[mf][nf][0]), "+f"(acc[mf][nf][1]),
                          "+f"(acc[mf][nf][2]), "+f"(acc[mf][nf][3])
                        : "r"(a[mf][0]), "r"(a[mf][1]), "r"(a[mf][2]), "r"(a[mf][3]),
                          "r"(b[nf][0]), "r"(b[nf][1]));
                }
        }
    };

    // -------- prologue: fill buffer 0 --------
    {
        float4 wq[4], tp[4];
        gather_half(0, 0, wq, tp);
        finish_half(0, wq, tp, Pb[0]);
        gather_half(0, 1, wq, tp);
        finish_half(1, wq, tp, Pb[0]);
        cp_weights(0, Wb[0]);
        asm volatile("cp.async.commit_group;" ::: "memory");
    }

    // -------- mainloop --------
    #pragma unroll 1
    for (int it = 0; it < NITER; ++it) {
        int b = it & 1;
        uint32_t Wt = Wb[b],   Pt = Pb[b];
        uint32_t Wn = Wb[b^1], Pn = Pb[b^1];

        asm volatile("cp.async.wait_group 0;" ::: "memory");
        __syncthreads();

        float4 wq[4], tp[4];
        bool more = (it + 1 < NITER);
        if (more) {
            cp_weights(it + 1, Wn);
            asm volatile("cp.async.commit_group;" ::: "memory");
            gather_half(it + 1, 0, wq, tp);      // long-latency LDGs issued
        }
        mma_half(Wt, Pt, 0);
        if (more) {
            finish_half(0, wq, tp, Pn);
            gather_half(it + 1, 1, wq, tp);
        }
        mma_half(Wt, Pt, 2);
        if (more) {
            finish_half(1, wq, tp, Pn);
        }
    }

    // -------- epilogue: D[o][pixel], coalesced float2 stores --------
    int nimg   = m0 >> 12;
    int pixoff = m0 & 4095;
    float* ob  = out + (size_t)nimg * (OUTC * 4096) + pixoff;
    #pragma unroll
    for (int mf = 0; mf < 4; ++mf) {
        #pragma unroll
        for (int nf = 0; nf < 4; ++nf) {
            int o   = wm * 64 + mf * 16 + g;
            int col = wn * 32 + nf * 8 + 2 * tg;
            *(float2*)(ob + (size_t)o * 4096 + col) =
                make_float2(acc[mf][nf][0], acc[mf][nf][1]);
            *(float2*)(ob + (size_t)(o + 8) * 4096 + col) =
                make_float2(acc[mf][nf][2], acc[mf][nf][3]);
        }
    }
}

extern "C" void kernel_launch(void* const* d_in, const int* in_sizes, int n_in,
                              void* d_out, int out_size) {
    const float* x   = (const float*)d_in[0];
    const float* off = (const float*)d_in[1];
    const float* w   = (const float*)d_in[2];
    float* out = (float*)d_out;

    cudaFuncSetAttribute(fused_kernel, cudaFuncAttributeMaxDynamicSharedMemorySize, SMEM_BYTES);

    prep_kernel<<<(KK * M_ + 255) / 256, 256>>>(off);
    wprep_kernel<<<(OUTC * RDIM + 255) / 256, 256>>>(w);
    fused_kernel<<<M_ / 128, 512, SMEM_BYTES>>>(x, out);
}